// round 2
// baseline (speedup 1.0000x reference)
#include <cuda_runtime.h>
#include <cstdint>

#define ROIS 128
#define CHN  512
#define KDIM 25088
#define HID  4096
#define KS1  9
#define KS2  8

// ---- scratch (device globals: no allocation allowed in kernel_launch) ----
__device__ float g_pooled[ROIS * KDIM];          // 12.25 MB
__device__ float g_part[KS1 * ROIS * HID];       // 18 MB (reused by GEMM2, KS2<KS1)
__device__ float g_fc6[ROIS * HID];
__device__ float g_fc7[ROIS * HID];

// ======================= RoI Pool =======================
// One warp per (roi, channel); lanes = w (W=32 exactly -> fully coalesced rows).
// Vertical band maxes in regs, horizontal maxes via smem exchange.
__global__ void roi_pool_kernel(const float* __restrict__ x,
                                const float* __restrict__ rois,
                                const int*   __restrict__ roi_idx,
                                float*       __restrict__ out)
{
    int wg   = (blockIdx.x * blockDim.x + threadIdx.x) >> 5;
    int lane = threadIdx.x & 31;
    if (wg >= ROIS * CHN) return;
    int r = wg >> 9;          // / 512
    int c = wg & 511;

    // rois stored [y1,x1,y2,x2]; reference uses xyxy = cols [1,0,3,2]
    float y1 = rois[r*4+0], x1 = rois[r*4+1], y2 = rois[r*4+2], x2 = rois[r*4+3];
    float sw = rintf(x1 * 0.0625f), sh = rintf(y1 * 0.0625f);
    float ew = rintf(x2 * 0.0625f), eh = rintf(y2 * 0.0625f);
    float bw = fmaxf(ew - sw + 1.0f, 1.0f) * (1.0f / 7.0f);
    float bh = fmaxf(eh - sh + 1.0f, 1.0f) * (1.0f / 7.0f);

    const float* feat = x + ((size_t)(roi_idx[r] * CHN + c) << 10);  // 32*32

    float m[7];
    #pragma unroll
    for (int ph = 0; ph < 7; ph++) {
        float hs = fminf(fmaxf(floorf(ph * bh) + sh, 0.f), 32.f);
        float he = fminf(fmaxf(ceilf((ph + 1) * bh) + sh, 0.f), 32.f);
        int h0 = (int)hs, h1 = (int)he;
        float v = -INFINITY;
        for (int h = h0; h < h1; h++) v = fmaxf(v, feat[(h << 5) + lane]);
        m[ph] = v;
    }

    __shared__ float s[8][7][32];
    int wl = threadIdx.x >> 5;
    #pragma unroll
    for (int ph = 0; ph < 7; ph++) s[wl][ph][lane] = m[ph];
    __syncwarp();

    for (int o = lane; o < 49; o += 32) {
        int ph = o / 7, pw = o - ph * 7;
        float wsb = fminf(fmaxf(floorf(pw * bw) + sw, 0.f), 32.f);
        float web = fminf(fmaxf(ceilf((pw + 1) * bw) + sw, 0.f), 32.f);
        int w0 = (int)wsb, w1 = (int)web;
        float v = -INFINITY;
        for (int w2 = w0; w2 < w1; w2++) v = fmaxf(v, s[wl][ph][w2]);
        if (v == -INFINITY) v = 0.f;   // empty bin -> 0 (torchvision semantics)
        out[(size_t)r * KDIM + c * 49 + o] = v;
    }
}

// ======================= TF32 GEMM (split-K) =======================
__device__ __forceinline__ void cp16(void* smem_dst, const void* gsrc) {
    uint32_t s = (uint32_t)__cvta_generic_to_shared(smem_dst);
    asm volatile("cp.async.cg.shared.global [%0], [%1], 16;" :: "r"(s), "l"(gsrc));
}
__device__ __forceinline__ uint32_t f2tf(float f) {
    uint32_t u; asm("cvt.rna.tf32.f32 %0, %1;" : "=r"(u) : "f"(f)); return u;
}

// A: [128, K] row-major. B: [K, N] row-major. Cp: [ksplit][128][N] partials.
// BM=128, BN=128, BK=16. 8 warps, each 64x32. Double-buffered cp.async.
__global__ void __launch_bounds__(256, 2)
gemm_tf32_kernel(const float* __restrict__ A, const float* __restrict__ B,
                 float* __restrict__ Cp, int K, int N,
                 int iters_per_split, int total_iters)
{
    __shared__ float As[2][128 * 20];   // pad 20: conflict-free A frag LDS
    __shared__ float Bs[2][16 * 136];   // pad 136: conflict-free B frag LDS

    int tid   = threadIdx.x;
    int n0    = blockIdx.x * 128;
    int split = blockIdx.y;
    int it0   = split * iters_per_split;
    int iters = min(iters_per_split, total_iters - it0);
    if (iters < 0) iters = 0;

    int w = tid >> 5, lane = tid & 31;
    int wm = (w >> 2) * 64, wn = (w & 3) * 32;
    int gid = lane >> 2, tig = lane & 3;

    float acc[4][4][4];
    #pragma unroll
    for (int i = 0; i < 4; i++)
        #pragma unroll
        for (int j = 0; j < 4; j++)
            #pragma unroll
            for (int q = 0; q < 4; q++) acc[i][j][q] = 0.f;

    auto load_tile = [&](int it, int buf) {
        int k0 = (it0 + it) << 4;
        #pragma unroll
        for (int l = 0; l < 2; l++) {                       // A: 128x16
            int ch = tid + (l << 8);
            int row = ch >> 2, c4 = (ch & 3) << 2;
            cp16(&As[buf][row * 20 + c4], A + (size_t)row * K + k0 + c4);
        }
        #pragma unroll
        for (int l = 0; l < 2; l++) {                       // B: 16x128
            int ch = tid + (l << 8);
            int row = ch >> 5, c4 = (ch & 31) << 2;
            cp16(&Bs[buf][row * 136 + c4], B + (size_t)(k0 + row) * N + n0 + c4);
        }
        asm volatile("cp.async.commit_group;");
    };

    int buf = 0;
    if (iters > 0) load_tile(0, 0);
    for (int it = 0; it < iters; it++) {
        bool more = (it + 1 < iters);
        if (more) {
            load_tile(it + 1, buf ^ 1);
            asm volatile("cp.async.wait_group 1;");
        } else {
            asm volatile("cp.async.wait_group 0;");
        }
        __syncthreads();
        const float* as = As[buf];
        const float* bp = Bs[buf];
        #pragma unroll
        for (int ks = 0; ks < 2; ks++) {
            int kk = ks << 3;
            uint32_t af[4][4], bf[4][2];
            #pragma unroll
            for (int mi = 0; mi < 4; mi++) {
                int rm = wm + (mi << 4);
                af[mi][0] = f2tf(as[(rm + gid)     * 20 + kk + tig]);
                af[mi][1] = f2tf(as[(rm + gid + 8) * 20 + kk + tig]);
                af[mi][2] = f2tf(as[(rm + gid)     * 20 + kk + tig + 4]);
                af[mi][3] = f2tf(as[(rm + gid + 8) * 20 + kk + tig + 4]);
            }
            #pragma unroll
            for (int ni = 0; ni < 4; ni++) {
                int cb = wn + (ni << 3);
                bf[ni][0] = f2tf(bp[(kk + tig)     * 136 + cb + gid]);
                bf[ni][1] = f2tf(bp[(kk + tig + 4) * 136 + cb + gid]);
            }
            #pragma unroll
            for (int mi = 0; mi < 4; mi++)
                #pragma unroll
                for (int ni = 0; ni < 4; ni++) {
                    asm volatile(
                        "mma.sync.aligned.m16n8k8.row.col.f32.tf32.tf32.f32 "
                        "{%0,%1,%2,%3}, {%4,%5,%6,%7}, {%8,%9}, {%0,%1,%2,%3};\n"
                        : "+f"(acc[mi][ni][0]), "+f"(acc[mi][ni][1]),
                          "+f"(acc[mi][ni][2]), "+f"(acc[mi][ni][3])
                        : "r"(af[mi][0]), "r"(af[mi][1]), "r"(af[mi][2]), "r"(af[mi][3]),
                          "r"(bf[ni][0]), "r"(bf[ni][1]));
                }
        }
        __syncthreads();
        buf ^= 1;
    }

    // epilogue: write partials (zeros if iters==0 so reduction stays correct)
    float* cbase = Cp + (size_t)split * 128 * N + n0;
    #pragma unroll
    for (int mi = 0; mi < 4; mi++) {
        int r0 = wm + (mi << 4) + gid;
        #pragma unroll
        for (int ni = 0; ni < 4; ni++) {
            int cc = wn + (ni << 3) + (tig << 1);
            *(float2*)(cbase + (size_t)r0 * N + cc)       = make_float2(acc[mi][ni][0], acc[mi][ni][1]);
            *(float2*)(cbase + (size_t)(r0 + 8) * N + cc) = make_float2(acc[mi][ni][2], acc[mi][ni][3]);
        }
    }
}

// ======================= split-K reduce + bias + ReLU =======================
__global__ void reduce_bias_relu(const float* __restrict__ part,
                                 const float* __restrict__ bias,
                                 float* __restrict__ out, int nsplit)
{
    int i = blockIdx.x * blockDim.x + threadIdx.x;   // float4 index, 128*4096/4 total
    const float4* p = (const float4*)part;
    float4 a = p[i];
    const int stride = ROIS * HID / 4;
    for (int s = 1; s < nsplit; s++) {
        float4 t = p[i + (size_t)s * stride];
        a.x += t.x; a.y += t.y; a.z += t.z; a.w += t.w;
    }
    float4 bb = ((const float4*)bias)[i & (HID / 4 - 1)];
    a.x = fmaxf(a.x + bb.x, 0.f);
    a.y = fmaxf(a.y + bb.y, 0.f);
    a.z = fmaxf(a.z + bb.z, 0.f);
    a.w = fmaxf(a.w + bb.w, 0.f);
    ((float4*)out)[i] = a;
}

// ======================= head GEMMs (loc + score, fp32) =======================
__global__ void head_kernel(const float* __restrict__ fc7,
                            const float* __restrict__ Wl, const float* __restrict__ bl,
                            const float* __restrict__ Wsc, const float* __restrict__ bsc,
                            float* __restrict__ out)
{
    int e = blockIdx.x * blockDim.x + threadIdx.x;
    if (e >= ROIS * 105) return;
    int r = e / 105, j = e - r * 105;
    const float* wp; int stride; float b; int oidx;
    if (j < 84) { wp = Wl + j;        stride = 84; b = bl[j];       oidx = r * 84 + j; }
    else        { int jj = j - 84; wp = Wsc + jj; stride = 21; b = bsc[jj]; oidx = ROIS * 84 + r * 21 + jj; }
    const float* f = fc7 + (size_t)r * HID;
    float acc = b;
    #pragma unroll 8
    for (int k = 0; k < HID; k++) acc = fmaf(f[k], wp[(size_t)k * stride], acc);
    out[oidx] = acc;
}

// ======================= launch =======================
extern "C" void kernel_launch(void* const* d_in, const int* in_sizes, int n_in,
                              void* d_out, int out_size)
{
    const float* x    = (const float*)d_in[0];
    const float* rois = (const float*)d_in[1];
    const int*   ridx = (const int*)  d_in[2];
    const float* W1   = (const float*)d_in[3];
    const float* b1   = (const float*)d_in[4];
    const float* W2   = (const float*)d_in[5];
    const float* b2   = (const float*)d_in[6];
    const float* Wl   = (const float*)d_in[7];
    const float* bl   = (const float*)d_in[8];
    const float* Wsc  = (const float*)d_in[9];
    const float* bsc  = (const float*)d_in[10];
    float* out = (float*)d_out;

    float *pooled, *part, *fc6, *fc7;
    cudaGetSymbolAddress((void**)&pooled, g_pooled);
    cudaGetSymbolAddress((void**)&part,   g_part);
    cudaGetSymbolAddress((void**)&fc6,    g_fc6);
    cudaGetSymbolAddress((void**)&fc7,    g_fc7);

    // 1) RoI pool: 128*512 warps
    roi_pool_kernel<<<(ROIS * CHN * 32) / 256, 256>>>(x, rois, ridx, pooled);

    // 2) fc6 = relu(pooled @ W1 + b1): K=25088 (1568 BK-iters), 9-way split-K
    gemm_tf32_kernel<<<dim3(HID / 128, KS1), 256>>>(pooled, W1, part, KDIM, HID, 175, KDIM / 16);
    reduce_bias_relu<<<(ROIS * HID / 4) / 256, 256>>>(part, b1, fc6, KS1);

    // 3) fc7 = relu(fc6 @ W2 + b2): K=4096 (256 iters), 8-way split-K
    gemm_tf32_kernel<<<dim3(HID / 128, KS2), 256>>>(fc6, W2, part, HID, HID, 32, HID / 16);
    reduce_bias_relu<<<(ROIS * HID / 4) / 256, 256>>>(part, b2, fc7, KS2);

    // 4) heads: [128,84] locs then [128,21] scores, concatenated in d_out
    head_kernel<<<105, 128>>>(fc7, Wl, bl, Wsc, bsc, out);
}